// round 15
// baseline (speedup 1.0000x reference)
#include <cuda_runtime.h>
#include <cuda_fp16.h>
#include <cuda_bf16.h>

#define N_NODES 50000
#define DIM     128
#define N_EDGES 800000
#define TILE    512
#define TILES_PER_G 98          // ceil(50000/512)
#define N_TILES (2 * TILES_PER_G)
#define GM      128             // GEMM block M
#define NBLK    ((N_NODES + GM - 1) / GM)   // 391

// ---------------------------------------------------------------------------
// Scratch (device globals — no allocation allowed in kernel_launch)
// ---------------------------------------------------------------------------
__device__ int    g_cnt [2 * N_NODES];
__device__ int    g_offs[2 * (N_NODES + 1)];
__device__ int    g_cur [2 * N_NODES];
__device__ int    g_csr [2 * N_EDGES];
__device__ float  g_dinv[2 * N_NODES];
__device__ __half g_x16A[N_NODES * DIM];     // fp16(x1)
__device__ __half g_x16B[N_NODES * DIM];     // fp16(x2)
__device__ __half g_hsA [N_NODES * DIM];     // (x @ W) * dinv[row]  (fp16), graph 1
__device__ __half g_hsB [N_NODES * DIM];     // graph 2
__device__ __half g_h16A[N_NODES * DIM];     // hidden activations (fp16), graph 1
__device__ __half g_h16B[N_NODES * DIM];     // graph 2
__device__ int    g_tilesum [N_TILES];
__device__ int    g_tilebase[N_TILES];
// fp16 B fragments, nb-paired, m16n8k16 (same layout as R14)
__device__ uint4  g_Bq[2 * 2048];

// ---------------------------------------------------------------------------
// helpers
// ---------------------------------------------------------------------------
__device__ __forceinline__ void mma16(float c[4], const unsigned a[4],
                                      unsigned b0, unsigned b1) {
    asm volatile(
        "mma.sync.aligned.m16n8k16.row.col.f32.f16.f16.f32 "
        "{%0,%1,%2,%3}, {%4,%5,%6,%7}, {%8,%9}, {%0,%1,%2,%3};"
        : "+f"(c[0]), "+f"(c[1]), "+f"(c[2]), "+f"(c[3])
        : "r"(a[0]), "r"(a[1]), "r"(a[2]), "r"(a[3]), "r"(b0), "r"(b1));
}

__device__ __forceinline__ unsigned pack_h2(float x, float y) {
    __half2 h = __floats2half2_rn(x, y);
    return *(unsigned*)&h;
}

// ---------------------------------------------------------------------------
// Prep: convert x1/x2 to fp16 AND zero cnt (fused). 1.6M threads.
// ---------------------------------------------------------------------------
__global__ void k_prep0(const float4* __restrict__ x1, const float4* __restrict__ x2) {
    const int Q = N_NODES * DIM / 8;   // 800000 (8 floats per thread)
    int i = blockIdx.x * blockDim.x + threadIdx.x;
    if (i < 2 * Q) {
        const float4* src = (i < Q) ? x1 : x2;
        int j = (i < Q) ? i : i - Q;
        float4 v0 = __ldg(src + 2 * j);
        float4 v1 = __ldg(src + 2 * j + 1);
        uint4 o;
        o.x = pack_h2(v0.x, v0.y);
        o.y = pack_h2(v0.z, v0.w);
        o.z = pack_h2(v1.x, v1.y);
        o.w = pack_h2(v1.z, v1.w);
        ((uint4*)((i < Q) ? g_x16A : g_x16B))[j] = o;
    }
    if (i < 2 * N_NODES) g_cnt[i] = 0;
}

// ---------------------------------------------------------------------------
// W pre-pack (fp16, m16n8k16 fragment-native, nb-paired) — unchanged
// ---------------------------------------------------------------------------
__global__ void k_packw(const float* __restrict__ W0, const float* __restrict__ W1) {
    int i = blockIdx.x * blockDim.x + threadIdx.x;
    if (i >= 4096) return;
    const float* W = (i < 2048) ? W0 : W1;
    int j   = i & 2047;
    int l4  = j & 3;
    int g   = (j >> 2) & 7;
    int nbp = (j >> 5) & 3;
    int wnh = (j >> 7) & 1;
    int ks  = (j >> 8) & 1;
    int kc  = j >> 9;
    int k0  = kc * 32 + ks * 16;
    int n0  = wnh * 64 + nbp * 16 + g;
    int n1  = n0 + 8;
    uint4 v;
    v.x = pack_h2(W[(k0 + l4 * 2)     * 128 + n0], W[(k0 + l4 * 2 + 1) * 128 + n0]);
    v.y = pack_h2(W[(k0 + 8 + l4 * 2) * 128 + n0], W[(k0 + 9 + l4 * 2) * 128 + n0]);
    v.z = pack_h2(W[(k0 + l4 * 2)     * 128 + n1], W[(k0 + l4 * 2 + 1) * 128 + n1]);
    v.w = pack_h2(W[(k0 + 8 + l4 * 2) * 128 + n1], W[(k0 + 9 + l4 * 2) * 128 + n1]);
    g_Bq[i] = v;
}

// ---------------------------------------------------------------------------
// CSR build (unchanged from R14)
// ---------------------------------------------------------------------------
__global__ void k_count2(const int* __restrict__ dst1, const int* __restrict__ dst2) {
    const int Q = N_EDGES / 4;
    int i = blockIdx.x * blockDim.x + threadIdx.x;
    int stride = gridDim.x * blockDim.x;
    for (; i < 2 * Q; i += stride) {
        int4 d;
        int base;
        if (i < Q) { d = __ldg((const int4*)dst1 + i); base = 0; }
        else       { d = __ldg((const int4*)dst2 + (i - Q)); base = N_NODES; }
        atomicAdd(&g_cnt[base + d.x], 1);
        atomicAdd(&g_cnt[base + d.y], 1);
        atomicAdd(&g_cnt[base + d.z], 1);
        atomicAdd(&g_cnt[base + d.w], 1);
    }
}

__global__ __launch_bounds__(TILE)
void k_blocksum() {
    int g  = blockIdx.x / TILES_PER_G;
    int lt = blockIdx.x % TILES_PER_G;
    int li = lt * TILE + threadIdx.x;
    int c = (li < N_NODES) ? g_cnt[g * N_NODES + li] : 0;

    int lane = threadIdx.x & 31, w = threadIdx.x >> 5;
    for (int o = 16; o > 0; o >>= 1) c += __shfl_down_sync(~0u, c, o);
    __shared__ int ws[TILE / 32];
    if (lane == 0) ws[w] = c;
    __syncthreads();
    if (threadIdx.x == 0) {
        int s = 0;
#pragma unroll
        for (int i = 0; i < TILE / 32; i++) s += ws[i];
        g_tilesum[blockIdx.x] = s;
    }
}

__global__ __launch_bounds__(256)
void k_scanbase() {
    __shared__ int s[N_TILES];
    if (threadIdx.x < N_TILES) s[threadIdx.x] = g_tilesum[threadIdx.x];
    __syncthreads();
    if (threadIdx.x < 2) {
        int g = threadIdx.x;
        int run = 0;
        for (int t = 0; t < TILES_PER_G; t++) {
            g_tilebase[g * TILES_PER_G + t] = run;
            run += s[g * TILES_PER_G + t];
        }
        g_offs[g * (N_NODES + 1) + N_NODES] = run;
    }
}

__global__ __launch_bounds__(TILE)
void k_offsets() {
    int g  = blockIdx.x / TILES_PER_G;
    int lt = blockIdx.x % TILES_PER_G;
    int li = lt * TILE + threadIdx.x;
    int c = (li < N_NODES) ? g_cnt[g * N_NODES + li] : 0;

    int lane = threadIdx.x & 31, w = threadIdx.x >> 5;
    int v = c;
#pragma unroll
    for (int o = 1; o < 32; o <<= 1) {
        int t = __shfl_up_sync(~0u, v, o);
        if (lane >= o) v += t;
    }
    __shared__ int ws[TILE / 32];
    if (lane == 31) ws[w] = v;
    __syncthreads();
    if (w == 0 && lane < TILE / 32) {
        int s = ws[lane];
#pragma unroll
        for (int o = 1; o < TILE / 32; o <<= 1) {
            int t = __shfl_up_sync(0xffff, s, o);
            if (lane >= o) s += t;
        }
        ws[lane] = s;
    }
    __syncthreads();
    int excl = v - c + (w > 0 ? ws[w - 1] : 0);

    if (li < N_NODES) {
        int off = g_tilebase[blockIdx.x] + excl;
        g_offs[g * (N_NODES + 1) + li] = off;
        g_cur [g * N_NODES + li] = off;
        g_dinv[g * N_NODES + li] = rsqrtf(1.0f + (float)c);
    }
}

__global__ void k_fill2(const int* __restrict__ src1, const int* __restrict__ dst1,
                        const int* __restrict__ src2, const int* __restrict__ dst2) {
    const int Q = N_EDGES / 4;
    int i = blockIdx.x * blockDim.x + threadIdx.x;
    int stride = gridDim.x * blockDim.x;
    for (; i < 2 * Q; i += stride) {
        int4 s, d;
        int nbase, ebase;
        if (i < Q) {
            s = __ldg((const int4*)src1 + i);
            d = __ldg((const int4*)dst1 + i);
            nbase = 0; ebase = 0;
        } else {
            s = __ldg((const int4*)src2 + (i - Q));
            d = __ldg((const int4*)dst2 + (i - Q));
            nbase = N_NODES; ebase = N_EDGES;
        }
        g_csr[ebase + atomicAdd(&g_cur[nbase + d.x], 1)] = s.x;
        g_csr[ebase + atomicAdd(&g_cur[nbase + d.y], 1)] = s.y;
        g_csr[ebase + atomicAdd(&g_cur[nbase + d.z], 1)] = s.z;
        g_csr[ebase + atomicAdd(&g_cur[nbase + d.w], 1)] = s.w;
    }
}

// ---------------------------------------------------------------------------
// GEMM (fp16 HMMA m16n8k16, fp16 A direct from gmem, ZERO in-loop cvt).
// hs[m][:] = (x[m][:] @ W) * rsqrt(1+cnt[m]). fp16 in, fp16 out.
// A fragment regs ARE the memory half2 pairs: a0 @ (k0+2*l4), a2 @ (k0+8+2*l4).
// ---------------------------------------------------------------------------
__global__ __launch_bounds__(256, 2)
void k_gemm_h16(const __half* __restrict__ xA, const __half* __restrict__ xB,
                const uint4* __restrict__ Bq, const int* __restrict__ cntAB,
                __half* __restrict__ hsA, __half* __restrict__ hsB) {
    __shared__ uint4 Bs[2048];   // full K of B fragments (32KB)

    const int tid  = threadIdx.x;
    const int lane = tid & 31;
    const int wid  = tid >> 5;
    const int g    = lane >> 2;
    const int l4   = lane & 3;
    const int wm   = (wid & 3) * 32;
    const int wnh  = wid >> 2;
    const int wn   = wnh * 64;

    const int gph  = (blockIdx.x >= NBLK) ? 1 : 0;
    const int m0   = (blockIdx.x - gph * NBLK) * GM;
    const __half* x = gph ? xB : xA;
    __half* hs      = gph ? hsB : hsA;
    const int* cnt  = cntAB + gph * N_NODES;

#pragma unroll
    for (int j = 0; j < 8; j++)
        Bs[tid + j * 256] = __ldg(Bq + tid + j * 256);
    __syncthreads();

    float c[2][8][4];
#pragma unroll
    for (int mf = 0; mf < 2; mf++)
#pragma unroll
        for (int nb = 0; nb < 8; nb++)
#pragma unroll
            for (int q = 0; q < 4; q++) c[mf][nb][q] = 0.0f;

    int R0 = m0 + wm + g;
    int R1 = R0 + 16;
    bool v00 = (R0     < N_NODES), v01 = (R0 + 8 < N_NODES);
    bool v10 = (R1     < N_NODES), v11 = (R1 + 8 < N_NODES);
    const __half* p00 = x + (size_t)R0 * 128 + l4 * 2;
    const __half* p01 = p00 + 8 * 128;
    const __half* p10 = x + (size_t)R1 * 128 + l4 * 2;
    const __half* p11 = p10 + 8 * 128;

#pragma unroll
    for (int kc = 0; kc < 4; kc++) {
#pragma unroll
        for (int ks = 0; ks < 2; ks++) {
            int k0 = kc * 32 + ks * 16;
            unsigned a0[4], a1[4];
            a0[0] = v00 ? __ldg((const unsigned*)(p00 + k0))     : 0u;
            a0[1] = v01 ? __ldg((const unsigned*)(p01 + k0))     : 0u;
            a0[2] = v00 ? __ldg((const unsigned*)(p00 + k0 + 8)) : 0u;
            a0[3] = v01 ? __ldg((const unsigned*)(p01 + k0 + 8)) : 0u;
            a1[0] = v10 ? __ldg((const unsigned*)(p10 + k0))     : 0u;
            a1[1] = v11 ? __ldg((const unsigned*)(p11 + k0))     : 0u;
            a1[2] = v10 ? __ldg((const unsigned*)(p10 + k0 + 8)) : 0u;
            a1[3] = v11 ? __ldg((const unsigned*)(p11 + k0 + 8)) : 0u;
#pragma unroll
            for (int nbp = 0; nbp < 4; nbp++) {
                uint4 bb = Bs[(((kc * 2 + ks) * 2 + wnh) * 4 + nbp) * 32 + lane];
                mma16(c[0][2 * nbp],     a0, bb.x, bb.y);
                mma16(c[0][2 * nbp + 1], a0, bb.z, bb.w);
                mma16(c[1][2 * nbp],     a1, bb.x, bb.y);
                mma16(c[1][2 * nbp + 1], a1, bb.z, bb.w);
            }
        }
    }

#pragma unroll
    for (int mf = 0; mf < 2; mf++) {
        int Ra = m0 + wm + mf * 16 + g;
        int Rb = Ra + 8;
        float d0 = (Ra < N_NODES) ? rsqrtf(1.0f + (float)__ldg(cnt + Ra)) : 0.f;
        float d1 = (Rb < N_NODES) ? rsqrtf(1.0f + (float)__ldg(cnt + Rb)) : 0.f;
#pragma unroll
        for (int nb = 0; nb < 8; nb++) {
            int col = wn + nb * 8 + 2 * l4;
            if (Ra < N_NODES) {
                __half2 o = __floats2half2_rn(c[mf][nb][0] * d0, c[mf][nb][1] * d0);
                *(__half2*)(hs + (size_t)Ra * 128 + col) = o;
            }
            if (Rb < N_NODES) {
                __half2 o = __floats2half2_rn(c[mf][nb][2] * d1, c[mf][nb][3] * d1);
                *(__half2*)(hs + (size_t)Rb * 128 + col) = o;
            }
        }
    }
}

// ---------------------------------------------------------------------------
// Aggregate + finalize (quarter-warp per node, templated output).
// MID=true : out fp16, ReLU (hidden layer).  MID=false: out fp32, no ReLU.
// out[n] = dinv[n] * (sum_e hs[src_e] + hs[n]) + b
// ---------------------------------------------------------------------------
__device__ __forceinline__ float4 h4tof4u(unsigned lo, unsigned hi) {
    float2 a = __half22float2(*(const __half2*)&lo);
    float2 b = __half22float2(*(const __half2*)&hi);
    return make_float4(a.x, a.y, b.x, b.y);
}
__device__ __forceinline__ void acc2(float4& X, float4& Y, uint4 v) {
    float4 l = h4tof4u(v.x, v.y);
    float4 h = h4tof4u(v.z, v.w);
    X.x += l.x; X.y += l.y; X.z += l.z; X.w += l.w;
    Y.x += h.x; Y.y += h.y; Y.z += h.z; Y.w += h.w;
}
__device__ __forceinline__ float4 f4add(float4 a, float4 b) {
    return make_float4(a.x + b.x, a.y + b.y, a.z + b.z, a.w + b.w);
}

template<bool MID>
__global__ __launch_bounds__(128)
void k_aggregate(const __half* __restrict__ hsA, const __half* __restrict__ hsB,
                 const float* __restrict__ b,
                 void* __restrict__ outA, void* __restrict__ outB) {
    int qid = blockIdx.x * 16 + (threadIdx.x >> 3);
    if (qid >= 2 * N_NODES) return;
    int gph  = (qid >= N_NODES) ? 1 : 0;
    int node = qid - gph * N_NODES;
    int h    = threadIdx.x & 7;

    const int*   offs = g_offs + gph * (N_NODES + 1);
    const int*   csr  = g_csr  + gph * N_EDGES;
    const uint4* hs4  = (const uint4*)(gph ? hsB : hsA);
    void* out = gph ? outB : outA;

    int beg = __ldg(offs + node);
    int end = __ldg(offs + node + 1);
    float dd = __ldg(g_dinv + qid);

    float4 A0 = make_float4(0.f, 0.f, 0.f, 0.f);
    float4 A1 = A0, A2 = A0, A3 = A0;
    float4 B0 = A0, B1 = A0, B2 = A0, B3 = A0;
    {
        uint4 vl = __ldg(hs4 + (size_t)node * 16 + h);
        uint4 vh = __ldg(hs4 + (size_t)node * 16 + 8 + h);
        acc2(A0, A1, vl);
        acc2(A2, A3, vh);
    }

    int e = beg;
    while (e < end && (e & 3)) {
        int s = __ldg(csr + e);
        acc2(B0, B1, __ldg(hs4 + (size_t)s * 16 + h));
        acc2(B2, B3, __ldg(hs4 + (size_t)s * 16 + 8 + h));
        e++;
    }
    for (; e + 4 <= end; e += 4) {
        int4 s = __ldg((const int4*)(csr + e));
        uint4 v0l = __ldg(hs4 + (size_t)s.x * 16 + h);
        uint4 v0h = __ldg(hs4 + (size_t)s.x * 16 + 8 + h);
        uint4 v1l = __ldg(hs4 + (size_t)s.y * 16 + h);
        uint4 v1h = __ldg(hs4 + (size_t)s.y * 16 + 8 + h);
        uint4 v2l = __ldg(hs4 + (size_t)s.z * 16 + h);
        uint4 v2h = __ldg(hs4 + (size_t)s.z * 16 + 8 + h);
        uint4 v3l = __ldg(hs4 + (size_t)s.w * 16 + h);
        uint4 v3h = __ldg(hs4 + (size_t)s.w * 16 + 8 + h);
        acc2(A0, A1, v0l); acc2(A2, A3, v0h);
        acc2(B0, B1, v1l); acc2(B2, B3, v1h);
        acc2(A0, A1, v2l); acc2(A2, A3, v2h);
        acc2(B0, B1, v3l); acc2(B2, B3, v3h);
    }
    for (; e < end; e++) {
        int s = __ldg(csr + e);
        acc2(A0, A1, __ldg(hs4 + (size_t)s * 16 + h));
        acc2(A2, A3, __ldg(hs4 + (size_t)s * 16 + 8 + h));
    }
    float4 L0 = f4add(A0, B0), L1 = f4add(A1, B1);
    float4 H0 = f4add(A2, B2), H1 = f4add(A3, B3);

    const float4* b4 = (const float4*)b;
    float4 bb0 = __ldg(b4 + 2 * h);
    float4 bb1 = __ldg(b4 + 2 * h + 1);
    float4 bb2 = __ldg(b4 + 2 * (h + 8));
    float4 bb3 = __ldg(b4 + 2 * (h + 8) + 1);
    float4 o0, o1, o2, o3;
    o0.x = fmaf(L0.x, dd, bb0.x); o0.y = fmaf(L0.y, dd, bb0.y);
    o0.z = fmaf(L0.z, dd, bb0.z); o0.w = fmaf(L0.w, dd, bb0.w);
    o1.x = fmaf(L1.x, dd, bb1.x); o1.y = fmaf(L1.y, dd, bb1.y);
    o1.z = fmaf(L1.z, dd, bb1.z); o1.w = fmaf(L1.w, dd, bb1.w);
    o2.x = fmaf(H0.x, dd, bb2.x); o2.y = fmaf(H0.y, dd, bb2.y);
    o2.z = fmaf(H0.z, dd, bb2.z); o2.w = fmaf(H0.w, dd, bb2.w);
    o3.x = fmaf(H1.x, dd, bb3.x); o3.y = fmaf(H1.y, dd, bb3.y);
    o3.z = fmaf(H1.z, dd, bb3.z); o3.w = fmaf(H1.w, dd, bb3.w);

    if (MID) {
        // ReLU + fp16 pack + 2 x STG.128
        o0.x = fmaxf(o0.x, 0.f); o0.y = fmaxf(o0.y, 0.f);
        o0.z = fmaxf(o0.z, 0.f); o0.w = fmaxf(o0.w, 0.f);
        o1.x = fmaxf(o1.x, 0.f); o1.y = fmaxf(o1.y, 0.f);
        o1.z = fmaxf(o1.z, 0.f); o1.w = fmaxf(o1.w, 0.f);
        o2.x = fmaxf(o2.x, 0.f); o2.y = fmaxf(o2.y, 0.f);
        o2.z = fmaxf(o2.z, 0.f); o2.w = fmaxf(o2.w, 0.f);
        o3.x = fmaxf(o3.x, 0.f); o3.y = fmaxf(o3.y, 0.f);
        o3.z = fmaxf(o3.z, 0.f); o3.w = fmaxf(o3.w, 0.f);
        uint4 uL, uH;
        uL.x = pack_h2(o0.x, o0.y); uL.y = pack_h2(o0.z, o0.w);
        uL.z = pack_h2(o1.x, o1.y); uL.w = pack_h2(o1.z, o1.w);
        uH.x = pack_h2(o2.x, o2.y); uH.y = pack_h2(o2.z, o2.w);
        uH.z = pack_h2(o3.x, o3.y); uH.w = pack_h2(o3.z, o3.w);
        uint4* orow = (uint4*)out + (size_t)node * 16;
        orow[h]     = uL;
        orow[8 + h] = uH;
    } else {
        float4* orow = (float4*)out + (size_t)node * 32;
        orow[2 * h]           = o0;
        orow[2 * h + 1]       = o1;
        orow[2 * (h + 8)]     = o2;
        orow[2 * (h + 8) + 1] = o3;
    }
}

// ---------------------------------------------------------------------------
// Launch. GEMM (layer 1) stays at launch index 3 for the ncu window
// (needs only g_cnt, ready after k_count2 at index 2; x16 from k_prep0 at 0).
// ---------------------------------------------------------------------------
extern "C" void kernel_launch(void* const* d_in, const int* in_sizes, int n_in,
                              void* d_out, int out_size) {
    const float* x1  = (const float*)d_in[0];
    const int*   ei1 = (const int*)  d_in[1];
    const float* x2  = (const float*)d_in[2];
    const int*   ei2 = (const int*)  d_in[3];
    const float* W0  = (const float*)d_in[4];
    const float* b0  = (const float*)d_in[5];
    const float* W1  = (const float*)d_in[6];
    const float* b1  = (const float*)d_in[7];
    float* out = (float*)d_out;

    const int* src1 = ei1;
    const int* dst1 = ei1 + N_EDGES;
    const int* src2 = ei2;
    const int* dst2 = ei2 + N_EDGES;

    __half *x16A, *x16B, *hsA, *hsB, *h16A, *h16B;
    uint4* Bq;
    int* cnt;
    cudaGetSymbolAddress((void**)&x16A, g_x16A);
    cudaGetSymbolAddress((void**)&x16B, g_x16B);
    cudaGetSymbolAddress((void**)&hsA,  g_hsA);
    cudaGetSymbolAddress((void**)&hsB,  g_hsB);
    cudaGetSymbolAddress((void**)&h16A, g_h16A);
    cudaGetSymbolAddress((void**)&h16B, g_h16B);
    cudaGetSymbolAddress((void**)&Bq,   g_Bq);
    cudaGetSymbolAddress((void**)&cnt,  g_cnt);

    const int PREP_GRID = (2 * (N_NODES * DIM / 8) + 255) / 256;   // 6250

    k_prep0<<<PREP_GRID, 256>>>((const float4*)x1, (const float4*)x2);   // 0
    k_packw<<<16, 256>>>(W0, W1);                                        // 1
    k_count2<<<1024, 256>>>(dst1, dst2);                                 // 2
    k_gemm_h16<<<2 * NBLK, 256>>>(x16A, x16B, Bq, cnt, hsA, hsB);        // 3 (ncu)
    k_blocksum<<<N_TILES, TILE>>>();                                     // 4
    k_scanbase<<<1, 256>>>();                                            // 5
    k_offsets<<<N_TILES, TILE>>>();                                      // 6
    k_fill2<<<1024, 256>>>(src1, dst1, src2, dst2);                      // 7

    const int AGG_GRID = (2 * N_NODES + 15) / 16;                        // 6250

    k_aggregate<true><<<AGG_GRID, 128>>>(hsA, hsB, b0, h16A, h16B);
    k_gemm_h16<<<2 * NBLK, 256>>>(h16A, h16B, Bq + 2048, cnt, hsA, hsB);
    k_aggregate<false><<<AGG_GRID, 128>>>(hsA, hsB, b1, out, out + (size_t)N_NODES * DIM);
}

// round 16
// speedup vs baseline: 1.1308x; 1.1308x over previous
#include <cuda_runtime.h>
#include <cuda_fp16.h>
#include <cuda_bf16.h>

#define N_NODES 50000
#define DIM     128
#define N_EDGES 800000
#define TILE    512
#define TILES_PER_G 98          // ceil(50000/512)
#define N_TILES (2 * TILES_PER_G)
#define GM      128             // GEMM block M
#define NBLK    ((N_NODES + GM - 1) / GM)   // 391

// ---------------------------------------------------------------------------
// Scratch (device globals — no allocation allowed in kernel_launch)
// ---------------------------------------------------------------------------
__device__ int    g_cnt [2 * N_NODES];
__device__ int    g_offs[2 * (N_NODES + 1)];
__device__ int    g_cur [2 * N_NODES];
__device__ int    g_csr [2 * N_EDGES];
__device__ float  g_dinv[2 * N_NODES];
__device__ __half g_hsA [N_NODES * DIM];     // (x @ W) * dinv[row]  (fp16), graph 1
__device__ __half g_hsB [N_NODES * DIM];     // graph 2
__device__ __half g_h16A[N_NODES * DIM];     // hidden activations (fp16), graph 1
__device__ __half g_h16B[N_NODES * DIM];     // graph 2
__device__ int    g_tilesum [N_TILES];
__device__ int    g_tilebase[N_TILES];
// fp16 B fragments, nb-paired, m16n8k16 (same layout as R14/R15)
__device__ uint4  g_Bq[2 * 2048];

// ---------------------------------------------------------------------------
// helpers
// ---------------------------------------------------------------------------
__device__ __forceinline__ void mma16(float c[4], const unsigned a[4],
                                      unsigned b0, unsigned b1) {
    asm volatile(
        "mma.sync.aligned.m16n8k16.row.col.f32.f16.f16.f32 "
        "{%0,%1,%2,%3}, {%4,%5,%6,%7}, {%8,%9}, {%0,%1,%2,%3};"
        : "+f"(c[0]), "+f"(c[1]), "+f"(c[2]), "+f"(c[3])
        : "r"(a[0]), "r"(a[1]), "r"(a[2]), "r"(a[3]), "r"(b0), "r"(b1));
}

__device__ __forceinline__ void ldsm_x4(unsigned a[4], unsigned saddr) {
    asm volatile(
        "ldmatrix.sync.aligned.m8n8.x4.shared.b16 {%0,%1,%2,%3}, [%4];"
        : "=r"(a[0]), "=r"(a[1]), "=r"(a[2]), "=r"(a[3]) : "r"(saddr));
}

__device__ __forceinline__ unsigned pack_h2(float x, float y) {
    __half2 h = __floats2half2_rn(x, y);
    return *(unsigned*)&h;
}

// ---------------------------------------------------------------------------
// W pre-pack (fp16, m16n8k16 fragment-native, nb-paired) — unchanged
// ---------------------------------------------------------------------------
__global__ void k_packw(const float* __restrict__ W0, const float* __restrict__ W1) {
    int i = blockIdx.x * blockDim.x + threadIdx.x;
    if (i >= 4096) return;
    const float* W = (i < 2048) ? W0 : W1;
    int j   = i & 2047;
    int l4  = j & 3;
    int g   = (j >> 2) & 7;
    int nbp = (j >> 5) & 3;
    int wnh = (j >> 7) & 1;
    int ks  = (j >> 8) & 1;
    int kc  = j >> 9;
    int k0  = kc * 32 + ks * 16;
    int n0  = wnh * 64 + nbp * 16 + g;
    int n1  = n0 + 8;
    uint4 v;
    v.x = pack_h2(W[(k0 + l4 * 2)     * 128 + n0], W[(k0 + l4 * 2 + 1) * 128 + n0]);
    v.y = pack_h2(W[(k0 + 8 + l4 * 2) * 128 + n0], W[(k0 + 9 + l4 * 2) * 128 + n0]);
    v.z = pack_h2(W[(k0 + l4 * 2)     * 128 + n1], W[(k0 + l4 * 2 + 1) * 128 + n1]);
    v.w = pack_h2(W[(k0 + 8 + l4 * 2) * 128 + n1], W[(k0 + 9 + l4 * 2) * 128 + n1]);
    g_Bq[i] = v;
}

// ---------------------------------------------------------------------------
// CSR build
// ---------------------------------------------------------------------------
__global__ void k_zero_cnt() {
    int i = blockIdx.x * blockDim.x + threadIdx.x;
    if (i < 2 * N_NODES) g_cnt[i] = 0;
}

__global__ void k_count2(const int* __restrict__ dst1, const int* __restrict__ dst2) {
    const int Q = N_EDGES / 4;
    int i = blockIdx.x * blockDim.x + threadIdx.x;
    int stride = gridDim.x * blockDim.x;
    for (; i < 2 * Q; i += stride) {
        int4 d;
        int base;
        if (i < Q) { d = __ldg((const int4*)dst1 + i); base = 0; }
        else       { d = __ldg((const int4*)dst2 + (i - Q)); base = N_NODES; }
        atomicAdd(&g_cnt[base + d.x], 1);
        atomicAdd(&g_cnt[base + d.y], 1);
        atomicAdd(&g_cnt[base + d.z], 1);
        atomicAdd(&g_cnt[base + d.w], 1);
    }
}

__global__ __launch_bounds__(TILE)
void k_blocksum() {
    int g  = blockIdx.x / TILES_PER_G;
    int lt = blockIdx.x % TILES_PER_G;
    int li = lt * TILE + threadIdx.x;
    int c = (li < N_NODES) ? g_cnt[g * N_NODES + li] : 0;

    int lane = threadIdx.x & 31, w = threadIdx.x >> 5;
    for (int o = 16; o > 0; o >>= 1) c += __shfl_down_sync(~0u, c, o);
    __shared__ int ws[TILE / 32];
    if (lane == 0) ws[w] = c;
    __syncthreads();
    if (threadIdx.x == 0) {
        int s = 0;
#pragma unroll
        for (int i = 0; i < TILE / 32; i++) s += ws[i];
        g_tilesum[blockIdx.x] = s;
    }
}

__global__ __launch_bounds__(256)
void k_scanbase() {
    __shared__ int s[N_TILES];
    if (threadIdx.x < N_TILES) s[threadIdx.x] = g_tilesum[threadIdx.x];
    __syncthreads();
    if (threadIdx.x < 2) {
        int g = threadIdx.x;
        int run = 0;
        for (int t = 0; t < TILES_PER_G; t++) {
            g_tilebase[g * TILES_PER_G + t] = run;
            run += s[g * TILES_PER_G + t];
        }
        g_offs[g * (N_NODES + 1) + N_NODES] = run;
    }
}

__global__ __launch_bounds__(TILE)
void k_offsets() {
    int g  = blockIdx.x / TILES_PER_G;
    int lt = blockIdx.x % TILES_PER_G;
    int li = lt * TILE + threadIdx.x;
    int c = (li < N_NODES) ? g_cnt[g * N_NODES + li] : 0;

    int lane = threadIdx.x & 31, w = threadIdx.x >> 5;
    int v = c;
#pragma unroll
    for (int o = 1; o < 32; o <<= 1) {
        int t = __shfl_up_sync(~0u, v, o);
        if (lane >= o) v += t;
    }
    __shared__ int ws[TILE / 32];
    if (lane == 31) ws[w] = v;
    __syncthreads();
    if (w == 0 && lane < TILE / 32) {
        int s = ws[lane];
#pragma unroll
        for (int o = 1; o < TILE / 32; o <<= 1) {
            int t = __shfl_up_sync(0xffff, s, o);
            if (lane >= o) s += t;
        }
        ws[lane] = s;
    }
    __syncthreads();
    int excl = v - c + (w > 0 ? ws[w - 1] : 0);

    if (li < N_NODES) {
        int off = g_tilebase[blockIdx.x] + excl;
        g_offs[g * (N_NODES + 1) + li] = off;
        g_cur [g * N_NODES + li] = off;
        g_dinv[g * N_NODES + li] = rsqrtf(1.0f + (float)c);
    }
}

__global__ void k_fill2(const int* __restrict__ src1, const int* __restrict__ dst1,
                        const int* __restrict__ src2, const int* __restrict__ dst2) {
    const int Q = N_EDGES / 4;
    int i = blockIdx.x * blockDim.x + threadIdx.x;
    int stride = gridDim.x * blockDim.x;
    for (; i < 2 * Q; i += stride) {
        int4 s, d;
        int nbase, ebase;
        if (i < Q) {
            s = __ldg((const int4*)src1 + i);
            d = __ldg((const int4*)dst1 + i);
            nbase = 0; ebase = 0;
        } else {
            s = __ldg((const int4*)src2 + (i - Q));
            d = __ldg((const int4*)dst2 + (i - Q));
            nbase = N_NODES; ebase = N_EDGES;
        }
        g_csr[ebase + atomicAdd(&g_cur[nbase + d.x], 1)] = s.x;
        g_csr[ebase + atomicAdd(&g_cur[nbase + d.y], 1)] = s.y;
        g_csr[ebase + atomicAdd(&g_cur[nbase + d.z], 1)] = s.z;
        g_csr[ebase + atomicAdd(&g_cur[nbase + d.w], 1)] = s.w;
    }
}

// ---------------------------------------------------------------------------
// GEMM (fp16 HMMA m16n8k16; A staged in swizzled smem, fragments via ldmatrix).
// hs[m][:] = (x[m][:] @ W) * rsqrt(1+cnt[m]). fp16 output.
// Templated input: float (layer 1: cvt at fill) or __half (layer 2: pure copy).
// smem: A 32KB (full tile, filled once) + B 16KB (half-K, staged twice) = 48KB.
// A layout: As[r*16 + (c ^ (r&7))], r = row 0..127, c = 16B chunk 0..15.
// ldmatrix x4 per (mf,ks): conflict-free (8 rows -> 8 distinct chunk slots).
// ---------------------------------------------------------------------------
template<typename T>
__global__ __launch_bounds__(256, 2)
void k_gemm_h16(const T* __restrict__ xA, const T* __restrict__ xB,
                const uint4* __restrict__ Bq, const int* __restrict__ cntAB,
                __half* __restrict__ hsA, __half* __restrict__ hsB) {
    __shared__ uint4 As[2048];   // 128 rows x 16 chunks (32KB)
    __shared__ uint4 Bs[1024];   // half of B (16KB)

    const int tid  = threadIdx.x;
    const int lane = tid & 31;
    const int wid  = tid >> 5;
    const int g    = lane >> 2;
    const int l4   = lane & 3;
    const int wm   = (wid & 3) * 32;
    const int wnh  = wid >> 2;
    const int wn   = wnh * 64;

    const int gph  = (blockIdx.x >= NBLK) ? 1 : 0;
    const int m0   = (blockIdx.x - gph * NBLK) * GM;
    const T* x     = gph ? xB : xA;
    __half* hs     = gph ? hsB : hsA;
    const int* cnt = cntAB + gph * N_NODES;

    // ---- Fill A tile (once, swizzled) ----
#pragma unroll
    for (int i = 0; i < 8; i++) {
        int f = i * 256 + tid;
        int r = f >> 4;
        int c = f & 15;
        int R = m0 + r;
        uint4 v = make_uint4(0u, 0u, 0u, 0u);
        if (R < N_NODES) {
            if constexpr (sizeof(T) == 4) {
                const float4* p = (const float4*)((const float*)x + (size_t)R * 128 + c * 8);
                float4 v0 = __ldg(p);
                float4 v1 = __ldg(p + 1);
                v.x = pack_h2(v0.x, v0.y);
                v.y = pack_h2(v0.z, v0.w);
                v.z = pack_h2(v1.x, v1.y);
                v.w = pack_h2(v1.z, v1.w);
            } else {
                v = __ldg((const uint4*)((const __half*)x + (size_t)R * 128) + c);
            }
        }
        As[r * 16 + (c ^ (r & 7))] = v;
    }

    // ---- Per-lane ldmatrix address components ----
    // lanes 0-7: matrix a0 (row+0, chunk c0); 8-15: a1 (row+8, c0);
    // 16-23: a2 (row+0, c0+1); 24-31: a3 (row+8, c0+1)
    const unsigned sA = (unsigned)__cvta_generic_to_shared(As);
    const int rloc  = wm + (lane & 7) + 8 * ((lane >> 3) & 1);  // row for mf=0
    const int cadd  = lane >> 4;                                 // chunk offset
    const int rmask = lane & 7;                                  // row & 7
    const unsigned aoff0 = sA + (unsigned)(rloc * 256);
    const unsigned aoff1 = aoff0 + 16 * 256;                     // mf=1: +16 rows

    float c[2][8][4];
#pragma unroll
    for (int mf = 0; mf < 2; mf++)
#pragma unroll
        for (int nb = 0; nb < 8; nb++)
#pragma unroll
            for (int q = 0; q < 4; q++) c[mf][nb][q] = 0.0f;

#pragma unroll
    for (int kc2 = 0; kc2 < 2; kc2++) {
        if (kc2) __syncthreads();       // protect Bs before overwrite
        // Stage half of B (kc = 2*kc2, 2*kc2+1)
#pragma unroll
        for (int j = 0; j < 4; j++)
            Bs[tid + j * 256] = __ldg(Bq + kc2 * 1024 + tid + j * 256);
        __syncthreads();                // also covers A fill on first pass

#pragma unroll
        for (int kl = 0; kl < 2; kl++) {
#pragma unroll
            for (int ks = 0; ks < 2; ks++) {
                int c0 = (kc2 * 2 + kl) * 4 + ks * 2;
                unsigned sw = (unsigned)(((c0 + cadd) ^ rmask) << 4);
                unsigned a0[4], a1[4];
                ldsm_x4(a0, aoff0 + sw);
                ldsm_x4(a1, aoff1 + sw);
#pragma unroll
                for (int nbp = 0; nbp < 4; nbp++) {
                    uint4 bb = Bs[(((kl * 2 + ks) * 2 + wnh) * 4 + nbp) * 32 + lane];
                    mma16(c[0][2 * nbp],     a0, bb.x, bb.y);
                    mma16(c[0][2 * nbp + 1], a0, bb.z, bb.w);
                    mma16(c[1][2 * nbp],     a1, bb.x, bb.y);
                    mma16(c[1][2 * nbp + 1], a1, bb.z, bb.w);
                }
            }
        }
    }

    // ---- Epilogue: scale by rsqrt(1+cnt[row]), store fp16 ----
#pragma unroll
    for (int mf = 0; mf < 2; mf++) {
        int Ra = m0 + wm + mf * 16 + g;
        int Rb = Ra + 8;
        float d0 = (Ra < N_NODES) ? rsqrtf(1.0f + (float)__ldg(cnt + Ra)) : 0.f;
        float d1 = (Rb < N_NODES) ? rsqrtf(1.0f + (float)__ldg(cnt + Rb)) : 0.f;
#pragma unroll
        for (int nb = 0; nb < 8; nb++) {
            int col = wn + nb * 8 + 2 * l4;
            if (Ra < N_NODES) {
                __half2 o = __floats2half2_rn(c[mf][nb][0] * d0, c[mf][nb][1] * d0);
                *(__half2*)(hs + (size_t)Ra * 128 + col) = o;
            }
            if (Rb < N_NODES) {
                __half2 o = __floats2half2_rn(c[mf][nb][2] * d1, c[mf][nb][3] * d1);
                *(__half2*)(hs + (size_t)Rb * 128 + col) = o;
            }
        }
    }
}

// ---------------------------------------------------------------------------
// Aggregate + finalize (quarter-warp per node, templated output) — as R15.
// MID=true : out fp16, ReLU (hidden layer).  MID=false: out fp32, no ReLU.
// ---------------------------------------------------------------------------
__device__ __forceinline__ float4 h4tof4u(unsigned lo, unsigned hi) {
    float2 a = __half22float2(*(const __half2*)&lo);
    float2 b = __half22float2(*(const __half2*)&hi);
    return make_float4(a.x, a.y, b.x, b.y);
}
__device__ __forceinline__ void acc2(float4& X, float4& Y, uint4 v) {
    float4 l = h4tof4u(v.x, v.y);
    float4 h = h4tof4u(v.z, v.w);
    X.x += l.x; X.y += l.y; X.z += l.z; X.w += l.w;
    Y.x += h.x; Y.y += h.y; Y.z += h.z; Y.w += h.w;
}
__device__ __forceinline__ float4 f4add(float4 a, float4 b) {
    return make_float4(a.x + b.x, a.y + b.y, a.z + b.z, a.w + b.w);
}

template<bool MID>
__global__ __launch_bounds__(128)
void k_aggregate(const __half* __restrict__ hsA, const __half* __restrict__ hsB,
                 const float* __restrict__ b,
                 void* __restrict__ outA, void* __restrict__ outB) {
    int qid = blockIdx.x * 16 + (threadIdx.x >> 3);
    if (qid >= 2 * N_NODES) return;
    int gph  = (qid >= N_NODES) ? 1 : 0;
    int node = qid - gph * N_NODES;
    int h    = threadIdx.x & 7;

    const int*   offs = g_offs + gph * (N_NODES + 1);
    const int*   csr  = g_csr  + gph * N_EDGES;
    const uint4* hs4  = (const uint4*)(gph ? hsB : hsA);
    void* out = gph ? outB : outA;

    int beg = __ldg(offs + node);
    int end = __ldg(offs + node + 1);
    float dd = __ldg(g_dinv + qid);

    float4 A0 = make_float4(0.f, 0.f, 0.f, 0.f);
    float4 A1 = A0, A2 = A0, A3 = A0;
    float4 B0 = A0, B1 = A0, B2 = A0, B3 = A0;
    {
        uint4 vl = __ldg(hs4 + (size_t)node * 16 + h);
        uint4 vh = __ldg(hs4 + (size_t)node * 16 + 8 + h);
        acc2(A0, A1, vl);
        acc2(A2, A3, vh);
    }

    int e = beg;
    while (e < end && (e & 3)) {
        int s = __ldg(csr + e);
        acc2(B0, B1, __ldg(hs4 + (size_t)s * 16 + h));
        acc2(B2, B3, __ldg(hs4 + (size_t)s * 16 + 8 + h));
        e++;
    }
    for (; e + 4 <= end; e += 4) {
        int4 s = __ldg((const int4*)(csr + e));
        uint4 v0l = __ldg(hs4 + (size_t)s.x * 16 + h);
        uint4 v0h = __ldg(hs4 + (size_t)s.x * 16 + 8 + h);
        uint4 v1l = __ldg(hs4 + (size_t)s.y * 16 + h);
        uint4 v1h = __ldg(hs4 + (size_t)s.y * 16 + 8 + h);
        uint4 v2l = __ldg(hs4 + (size_t)s.z * 16 + h);
        uint4 v2h = __ldg(hs4 + (size_t)s.z * 16 + 8 + h);
        uint4 v3l = __ldg(hs4 + (size_t)s.w * 16 + h);
        uint4 v3h = __ldg(hs4 + (size_t)s.w * 16 + 8 + h);
        acc2(A0, A1, v0l); acc2(A2, A3, v0h);
        acc2(B0, B1, v1l); acc2(B2, B3, v1h);
        acc2(A0, A1, v2l); acc2(A2, A3, v2h);
        acc2(B0, B1, v3l); acc2(B2, B3, v3h);
    }
    for (; e < end; e++) {
        int s = __ldg(csr + e);
        acc2(A0, A1, __ldg(hs4 + (size_t)s * 16 + h));
        acc2(A2, A3, __ldg(hs4 + (size_t)s * 16 + 8 + h));
    }
    float4 L0 = f4add(A0, B0), L1 = f4add(A1, B1);
    float4 H0 = f4add(A2, B2), H1 = f4add(A3, B3);

    const float4* b4 = (const float4*)b;
    float4 bb0 = __ldg(b4 + 2 * h);
    float4 bb1 = __ldg(b4 + 2 * h + 1);
    float4 bb2 = __ldg(b4 + 2 * (h + 8));
    float4 bb3 = __ldg(b4 + 2 * (h + 8) + 1);
    float4 o0, o1, o2, o3;
    o0.x = fmaf(L0.x, dd, bb0.x); o0.y = fmaf(L0.y, dd, bb0.y);
    o0.z = fmaf(L0.z, dd, bb0.z); o0.w = fmaf(L0.w, dd, bb0.w);
    o1.x = fmaf(L1.x, dd, bb1.x); o1.y = fmaf(L1.y, dd, bb1.y);
    o1.z = fmaf(L1.z, dd, bb1.z); o1.w = fmaf(L1.w, dd, bb1.w);
    o2.x = fmaf(H0.x, dd, bb2.x); o2.y = fmaf(H0.y, dd, bb2.y);
    o2.z = fmaf(H0.z, dd, bb2.z); o2.w = fmaf(H0.w, dd, bb2.w);
    o3.x = fmaf(H1.x, dd, bb3.x); o3.y = fmaf(H1.y, dd, bb3.y);
    o3.z = fmaf(H1.z, dd, bb3.z); o3.w = fmaf(H1.w, dd, bb3.w);

    if (MID) {
        o0.x = fmaxf(o0.x, 0.f); o0.y = fmaxf(o0.y, 0.f);
        o0.z = fmaxf(o0.z, 0.f); o0.w = fmaxf(o0.w, 0.f);
        o1.x = fmaxf(o1.x, 0.f); o1.y = fmaxf(o1.y, 0.f);
        o1.z = fmaxf(o1.z, 0.f); o1.w = fmaxf(o1.w, 0.f);
        o2.x = fmaxf(o2.x, 0.f); o2.y = fmaxf(o2.y, 0.f);
        o2.z = fmaxf(o2.z, 0.f); o2.w = fmaxf(o2.w, 0.f);
        o3.x = fmaxf(o3.x, 0.f); o3.y = fmaxf(o3.y, 0.f);
        o3.z = fmaxf(o3.z, 0.f); o3.w = fmaxf(o3.w, 0.f);
        uint4 uL, uH;
        uL.x = pack_h2(o0.x, o0.y); uL.y = pack_h2(o0.z, o0.w);
        uL.z = pack_h2(o1.x, o1.y); uL.w = pack_h2(o1.z, o1.w);
        uH.x = pack_h2(o2.x, o2.y); uH.y = pack_h2(o2.z, o2.w);
        uH.z = pack_h2(o3.x, o3.y); uH.w = pack_h2(o3.z, o3.w);
        uint4* orow = (uint4*)out + (size_t)node * 16;
        orow[h]     = uL;
        orow[8 + h] = uH;
    } else {
        float4* orow = (float4*)out + (size_t)node * 32;
        orow[2 * h]           = o0;
        orow[2 * h + 1]       = o1;
        orow[2 * (h + 8)]     = o2;
        orow[2 * (h + 8) + 1] = o3;
    }
}

// ---------------------------------------------------------------------------
// Launch. GEMM (layer 1) at launch index 3 for the ncu window.
// ---------------------------------------------------------------------------
extern "C" void kernel_launch(void* const* d_in, const int* in_sizes, int n_in,
                              void* d_out, int out_size) {
    const float* x1  = (const float*)d_in[0];
    const int*   ei1 = (const int*)  d_in[1];
    const float* x2  = (const float*)d_in[2];
    const int*   ei2 = (const int*)  d_in[3];
    const float* W0  = (const float*)d_in[4];
    const float* b0  = (const float*)d_in[5];
    const float* W1  = (const float*)d_in[6];
    const float* b1  = (const float*)d_in[7];
    float* out = (float*)d_out;

    const int* src1 = ei1;
    const int* dst1 = ei1 + N_EDGES;
    const int* src2 = ei2;
    const int* dst2 = ei2 + N_EDGES;

    __half *hsA, *hsB, *h16A, *h16B;
    uint4* Bq;
    int* cnt;
    cudaGetSymbolAddress((void**)&hsA,  g_hsA);
    cudaGetSymbolAddress((void**)&hsB,  g_hsB);
    cudaGetSymbolAddress((void**)&h16A, g_h16A);
    cudaGetSymbolAddress((void**)&h16B, g_h16B);
    cudaGetSymbolAddress((void**)&Bq,   g_Bq);
    cudaGetSymbolAddress((void**)&cnt,  g_cnt);

    k_packw<<<16, 256>>>(W0, W1);                                      // 0
    k_zero_cnt<<<(2 * N_NODES + 255) / 256, 256>>>();                  // 1
    k_count2<<<1024, 256>>>(dst1, dst2);                               // 2
    k_gemm_h16<float><<<2 * NBLK, 256>>>(x1, x2, Bq, cnt, hsA, hsB);   // 3 (ncu)
    k_blocksum<<<N_TILES, TILE>>>();                                   // 4
    k_scanbase<<<1, 256>>>();                                          // 5
    k_offsets<<<N_TILES, TILE>>>();                                    // 6
    k_fill2<<<1024, 256>>>(src1, dst1, src2, dst2);                    // 7

    const int AGG_GRID = (2 * N_NODES + 15) / 16;                      // 6250

    k_aggregate<true><<<AGG_GRID, 128>>>(hsA, hsB, b0, h16A, h16B);
    k_gemm_h16<__half><<<2 * NBLK, 256>>>(h16A, h16B, Bq + 2048, cnt, hsA, hsB);
    k_aggregate<false><<<AGG_GRID, 128>>>(hsA, hsB, b1, out, out + (size_t)N_NODES * DIM);
}